// round 17
// baseline (speedup 1.0000x reference)
#include <cuda_runtime.h>
#include <stdint.h>

#define NSTAGE 3
#define CH8_U2 1024u     // one 8KB chunk: [32 nt][32 lane] uint2 (fp16 b-frags, one k16 slab)
#define CH8_BYTES 8192u

// dynamic smem layout (bytes)
// ring mbars: full[3]@0,16,32 ; empty[3]@48,64,80
// slab mbars: 32 x 8B @ 128..384  (buf*16 + ktile)
#define OFF_T4 384u                               // float4 T[256]={b1,c',wt,cc} -> 4480
#define OFF_TT 4480u                              // t_range 25 f32 -> 4580
#define OFF_H0 4608u                              // 128x256 fp16 comp-major = 65536
#define OFF_H1 (OFF_H0 + 65536u)                  // 70144
#define OFF_S  (OFF_H1 + 65536u)                  // 135680
#define OFF_RING (OFF_S + 65536u)                 // 201216
#define DYN_SMEM (OFF_RING + NSTAGE * CH8_BYTES)  // 225792

// prep outputs
__device__ __align__(128) uint2 g_wblk[24 * 2048];  // 16KB-chunk images; used as 48 x 8KB halves
__device__ __align__(16) float g_M[256 * 256];      // M' = dt * (W2 @ W1), fp32
__device__ __align__(16) float4 g_T4[256];          // {b1, c'=dt*b2@W1, wt, cc=25*dt*b2}

// ---------- helpers ----------
__device__ __forceinline__ uint32_t smem_u32(const void* p) {
    uint32_t a;
    asm("{ .reg .u64 t; cvta.to.shared.u64 t, %1; cvt.u32.u64 %0, t; }" : "=r"(a) : "l"(p));
    return a;
}
__device__ __forceinline__ uint32_t pack_h2(float lo, float hi) {
    uint32_t r;
    asm("cvt.rn.f16x2.f32 %0, %1, %2;" : "=r"(r) : "f"(hi), "f"(lo));
    return r;
}
__device__ __forceinline__ uint32_t tanh_h2(uint32_t x) {
    uint32_t r;
    asm("tanh.approx.f16x2 %0, %1;" : "=r"(r) : "r"(x));
    return r;
}
__device__ __forceinline__ uint32_t hadd2(uint32_t a, uint32_t b) {
    uint32_t r;
    asm("add.rn.f16x2 %0, %1, %2;" : "=r"(r) : "r"(a), "r"(b));
    return r;
}

#define MBINIT(addr, cnt) \
    asm volatile("mbarrier.init.shared.b64 [%0], %1;" :: "r"(addr), "r"(cnt) : "memory")
#define MB_TX(addr, bytes) \
    asm volatile("mbarrier.arrive.expect_tx.shared.b64 _, [%0], %1;" :: "r"(addr), "r"(bytes) : "memory")
#define MB_ARRIVE(addr) \
    asm volatile("mbarrier.arrive.shared.b64 _, [%0];" :: "r"(addr) : "memory")

#define WAITP(addr, par) do { \
    uint32_t _m = (addr), _p = (par), _d; \
    asm volatile("{\n\t.reg .pred p;\n\t" \
        "mbarrier.try_wait.parity.acquire.cta.shared::cta.b64 p, [%1], %2;\n\t" \
        "selp.b32 %0, 1, 0, p;\n\t}" : "=r"(_d) : "r"(_m), "r"(_p) : "memory"); \
    if (!_d) { \
        asm volatile("{\n\t.reg .pred P1;\n\t" \
            "WL_%=:\n\t" \
            "mbarrier.try_wait.parity.acquire.cta.shared::cta.b64 P1, [%0], %1, 0x989680;\n\t" \
            "@P1 bra.uni WD_%=;\n\tbra.uni WL_%=;\n\tWD_%=:\n\t}" \
            :: "r"(_m), "r"(_p) : "memory"); \
    } \
} while (0)

#define WAITPR(addr, par) do { \
    uint32_t _m = (addr), _p = (par), _d; \
    asm volatile("{\n\t.reg .pred p;\n\t" \
        "mbarrier.try_wait.parity.relaxed.cta.shared::cta.b64 p, [%1], %2, 0x989680;\n\t" \
        "selp.b32 %0, 1, 0, p;\n\t}" : "=r"(_d) : "r"(_m), "r"(_p) : "memory"); \
    if (!_d) { \
        asm volatile("{\n\t.reg .pred P1;\n\t" \
            "WL_%=:\n\t" \
            "mbarrier.try_wait.parity.relaxed.cta.shared::cta.b64 P1, [%0], %1, 0x989680;\n\t" \
            "@P1 bra.uni WD_%=;\n\tbra.uni WL_%=;\n\tWD_%=:\n\t}" \
            :: "r"(_m), "r"(_p) : "memory"); \
    } \
} while (0)

#define BAR1() asm volatile("bar.sync 1, 512;" ::: "memory")

__device__ __forceinline__ void bulk_g2s(uint32_t dst, const void* src, uint32_t bytes, uint32_t mbar) {
    asm volatile(
        "cp.async.bulk.shared::cluster.global.mbarrier::complete_tx::bytes [%0], [%1], %2, [%3];"
        :: "r"(dst), "l"(src), "r"(bytes), "r"(mbar) : "memory");
}

// mma.sync m16n8k16 f16->f32 (g=lane>>2, t=lane&3)
#define MMA16(d, ax, ay, az, aw, bx, by) \
    asm volatile("mma.sync.aligned.m16n8k16.row.col.f32.f16.f16.f32 " \
        "{%0,%1,%2,%3}, {%4,%5,%6,%7}, {%8,%9}, {%0,%1,%2,%3};" \
        : "+f"((d)[0]), "+f"((d)[1]), "+f"((d)[2]), "+f"((d)[3]) \
        : "r"(ax), "r"(ay), "r"(az), "r"(aw), "r"(bx), "r"(by))

// comp-major A-fragment layout: (row 0..127, colpair 0..127) in 16x8cp tiles.
__device__ __forceinline__ uint32_t zh_word(int row, int cp) {
    int tile = ((row >> 4) << 4) + (cp >> 3);
    int comp = ((row >> 3) & 1) + (((cp >> 2) & 1) << 1);
    int ln = ((row & 7) << 2) + (cp & 3);
    return (uint32_t)(tile * 128 + comp * 32 + ln);
}
__device__ __forceinline__ void zh_store_pair(uint32_t* ZB, int row, int cp, uint32_t v) {
    ZB[zh_word(row, cp)] = v;
}
__device__ __forceinline__ void s_accum(uint32_t* SB, int row, int cp, uint32_t h) {
    uint32_t idx = zh_word(row, cp);
    SB[idx] = hadd2(SB[idx], h);
}

// ---------- prep 1: M' = dt*(W2 @ W1), fp32, 4-way unrolled dot ----------
extern "C" __global__ void __launch_bounds__(256) ode_prep_mm(
    const float* __restrict__ W1, const float* __restrict__ W2,
    const float* __restrict__ t_range) {
    int k = blockIdx.x, n = threadIdx.x;
    float dt = t_range[1] - t_range[0];
    float s0 = 0, s1 = 0, s2 = 0, s3 = 0;
#pragma unroll 4
    for (int j = 0; j < 256; j += 4) {
        s0 = fmaf(W2[k * 256 + j + 0], W1[(j + 0) * 256 + n], s0);
        s1 = fmaf(W2[k * 256 + j + 1], W1[(j + 1) * 256 + n], s1);
        s2 = fmaf(W2[k * 256 + j + 2], W1[(j + 2) * 256 + n], s2);
        s3 = fmaf(W2[k * 256 + j + 3], W1[(j + 3) * 256 + n], s3);
    }
    g_M[k * 256 + n] = dt * ((s0 + s1) + (s2 + s3));
}

// ---------- prep 2: T table {b1, c'=dt*(b2@W1), wt, cc=25*dt*b2} ----------
extern "C" __global__ void __launch_bounds__(256) ode_prep_T(
    const float* __restrict__ W1, const float* __restrict__ b1,
    const float* __restrict__ wt, const float* __restrict__ b2,
    const float* __restrict__ t_range) {
    int n = threadIdx.x;
    float dt = t_range[1] - t_range[0];
    float s0 = 0, s1 = 0, s2 = 0, s3 = 0;
#pragma unroll 4
    for (int j = 0; j < 256; j += 4) {
        s0 = fmaf(b2[j + 0], W1[(j + 0) * 256 + n], s0);
        s1 = fmaf(b2[j + 1], W1[(j + 1) * 256 + n], s1);
        s2 = fmaf(b2[j + 2], W1[(j + 2) * 256 + n], s2);
        s3 = fmaf(b2[j + 3], W1[(j + 3) * 256 + n], s3);
    }
    g_T4[n] = make_float4(b1[n], dt * ((s0 + s1) + (s2 + s3)), wt[n], 25.0f * dt * b2[n]);
}

// ---------- prep 3: pack fp16 b-frag k32-slab chunk images ----------
// chunk c = mat*8 + slab; sources: mat0 = W1, mat1 = g_M, mat2 = dt*W2.
// 16KB image = [2 kt][32 nt][32 lane] uint2 -> kt halves are self-contained 8KB k16 slabs.
extern "C" __global__ void __launch_bounds__(256) ode_prep_pack(
    const float* __restrict__ W1, const float* __restrict__ W2,
    const float* __restrict__ t_range) {
    int c = blockIdx.x, mat = c >> 3, slab = c & 7;
    float dt = t_range[1] - t_range[0];
    const float* src = (mat == 0) ? W1 : (mat == 1 ? g_M : W2);
    float scl = (mat == 2) ? dt : 1.0f;
    for (int e = threadIdx.x; e < 2048; e += 256) {
        int lane = e & 31, nt = (e >> 5) & 31, kt = e >> 10;
        int g = lane >> 2, t = lane & 3;
        int kb = slab * 32 + kt * 16, n = nt * 8 + g;
        uint2 v;
        v.x = pack_h2(scl * src[(kb + 2 * t) * 256 + n], scl * src[(kb + 2 * t + 1) * 256 + n]);
        v.y = pack_h2(scl * src[(kb + 2 * t + 8) * 256 + n], scl * src[(kb + 2 * t + 9) * 256 + n]);
        g_wblk[c * 2048 + e] = v;
    }
}

// ---------- GEMM pass: d += A(src buf) @ B(ring), k=256 over 16 k16 chunks ----------
// If gated, each kc waits for H slab (buf, kc) at parity spar before reading A.
__device__ __forceinline__ void gemm_pass(
    float (&d)[2][8][4], const char* smem, uint32_t sb, uint32_t a_off,
    int gated, int buf, uint32_t spar,
    int mi, int ni, int lane, uint32_t& cs, uint32_t& cp) {
    const uint32_t* A = (const uint32_t*)(smem + a_off);
    for (int kc = 0; kc < 16; kc++) {
        if (gated) WAITP(sb + 128u + (uint32_t)(buf * 16 + kc) * 8u, spar);
        WAITP(sb + 16u * cs, cp);
        const uint2* Bk = (const uint2*)(smem + OFF_RING + cs * CH8_BYTES);
        uint32_t a[2][4];
#pragma unroll
        for (int i = 0; i < 2; i++) {
            const uint32_t* Ab = A + (((mi * 2 + i) * 16 + kc) * 128) + lane;
            a[i][0] = Ab[0]; a[i][1] = Ab[32]; a[i][2] = Ab[64]; a[i][3] = Ab[96];
        }
        uint2 b[8];
#pragma unroll
        for (int j = 0; j < 8; j++) b[j] = Bk[(ni * 8 + j) * 32 + lane];
#pragma unroll
        for (int i = 0; i < 2; i++)
#pragma unroll
            for (int j = 0; j < 8; j++)
                MMA16(d[i][j], a[i][0], a[i][1], a[i][2], a[i][3], b[j].x, b[j].y);
        if (lane == 0) MB_ARRIVE(sb + 48u + 16u * cs);
        cs++; if (cs == NSTAGE) { cs = 0; cp ^= 1; }
    }
}

// ---------- main persistent kernel ----------
// u-space recurrence, u in accumulator registers. Per step: h=tanh(u+B_s) -> H_{s&1}
// published slab-by-slab via mbarriers (no CTA barrier in the loop!), S += h deferred
// past the arrive, then u += h@M' consuming slabs as they land.
// Safety (no WAR on H): a warp in epi_s implies it passed gemm_{s-1}, whose slab waits
// required ALL warps to arrive epi_{s-1}, which (program order) means all warps finished
// gemm_{s-2} = the last reader of H_{s&1}.
extern "C" __global__ void __launch_bounds__(544, 1) ode_main(
    const float* __restrict__ z0, const float* __restrict__ t_range,
    float* __restrict__ out) {
    extern __shared__ char smem[];
    const uint32_t sb = smem_u32(smem);
    const int tid = threadIdx.x, w = tid >> 5, lane = tid & 31;
    const int row0 = blockIdx.x * 128;

    uint32_t* H0 = (uint32_t*)(smem + OFF_H0);
    uint32_t* H1 = (uint32_t*)(smem + OFF_H1);
    uint32_t* SB = (uint32_t*)(smem + OFF_S);
    float4* sT4 = (float4*)(smem + OFF_T4);
    float* sTT = (float*)(smem + OFF_TT);

    const int mi = w >> 2, ni = w & 3;
    const int gid = lane >> 2, tig = lane & 3;

    if (tid == 0) {
        for (int s = 0; s < NSTAGE; s++) {
            MBINIT(sb + 16u * s, 1);         // ring full
            MBINIT(sb + 48u + 16u * s, 16);  // ring empty (16 compute warps)
        }
        for (int s = 0; s < 32; s++) MBINIT(sb + 128u + 8u * s, 128);  // slabs: 4 warps x 32 lanes
    }
    if (tid < 256) sT4[tid] = g_T4[tid];
    if (tid >= 256 && tid < 281) sTT[tid - 256] = t_range[tid - 256];
    for (int i = tid; i < 16384; i += 544) SB[i] = 0u;
    // per-warp init: z0 fragments -> fp16 image in H1 (A operand of GEMM0)
    if (w < 16) {
#pragma unroll
        for (int i = 0; i < 2; i++)
#pragma unroll
            for (int j = 0; j < 8; j++) {
                const int row = mi * 32 + i * 16 + gid;
                const int col = ni * 64 + j * 8 + 2 * tig;
                const int cpair = ni * 32 + j * 4 + tig;
                float2 v0 = *(const float2*)(z0 + (size_t)(row0 + row) * 256 + col);
                float2 v1 = *(const float2*)(z0 + (size_t)(row0 + row + 8) * 256 + col);
                zh_store_pair(H1, row, cpair, pack_h2(v0.x, v0.y));
                zh_store_pair(H1, row + 8, cpair, pack_h2(v1.x, v1.y));
            }
    }
    __syncthreads();

    if (w == 16) {
        // ---- producer: 432 8KB chunks = W1 halves 0-15, (M' 16-31) x25, W2' 32-47 ----
        if (lane == 0) {
            uint32_t es = 0, ep = 1;
            for (int i = 0; i < 432; i++) {
                int half = (i < 16) ? i : (i < 416 ? 16 + ((i - 16) & 15) : 32 + (i - 416));
                WAITPR(sb + 48u + 16u * es, ep);
                MB_TX(sb + 16u * es, CH8_BYTES);
                bulk_g2s(sb + OFF_RING + es * CH8_BYTES,
                         (const char*)g_wblk + (size_t)half * CH8_BYTES,
                         CH8_BYTES, sb + 16u * es);
                es++; if (es == NSTAGE) { es = 0; ep ^= 1; }
            }
        }
        return;
    }

    // ---- compute warps ----
    uint32_t cs = 0, cp = 0;
    float d[2][8][4];

    // GEMM0: u0 = z0 @ W1 (A in H1, ungated — covered by __syncthreads)
#pragma unroll
    for (int i = 0; i < 2; i++)
#pragma unroll
        for (int j = 0; j < 8; j++)
#pragma unroll
            for (int r = 0; r < 4; r++) d[i][j][r] = 0.0f;
    gemm_pass(d, smem, sb, OFF_H1, 0, 0, 0, mi, ni, lane, cs, cp);

    for (int s = 0; s < 25; s++) {
        const float sf = (float)s, t = sTT[s];
        const int buf = s & 1;
        uint32_t* HBuf = buf ? H1 : H0;
        const uint32_t spar = (uint32_t)((s >> 1) & 1);
        // ---- epilogue: h = tanh(u + b1 + s*c' + t*wt) -> HBuf, slab-by-slab ----
#pragma unroll
        for (int jp = 0; jp < 4; jp++) {
            uint32_t hh[2][2][2];
#pragma unroll
            for (int jj = 0; jj < 2; jj++) {
                const int j = 2 * jp + jj;
                const int col = ni * 64 + j * 8 + 2 * tig;
                const int cpair = ni * 32 + j * 4 + tig;
                float4 q0 = sT4[col], q1 = sT4[col + 1];
                float bw0 = fmaf(t, q0.z, fmaf(sf, q0.y, q0.x));
                float bw1 = fmaf(t, q1.z, fmaf(sf, q1.y, q1.x));
#pragma unroll
                for (int i = 0; i < 2; i++) {
                    const int row = mi * 32 + i * 16 + gid;
                    uint32_t h01 = tanh_h2(pack_h2(d[i][j][0] + bw0, d[i][j][1] + bw1));
                    uint32_t h23 = tanh_h2(pack_h2(d[i][j][2] + bw0, d[i][j][3] + bw1));
                    zh_store_pair(HBuf, row, cpair, h01);
                    zh_store_pair(HBuf, row + 8, cpair, h23);
                    hh[jj][i][0] = h01; hh[jj][i][1] = h23;
                }
            }
            MB_ARRIVE(sb + 128u + (uint32_t)(buf * 16 + 4 * ni + jp) * 8u);  // all 32 lanes
            // deferred S accumulation (overlaps consumers of this slab)
#pragma unroll
            for (int jj = 0; jj < 2; jj++) {
                const int j = 2 * jp + jj;
                const int cpair = ni * 32 + j * 4 + tig;
#pragma unroll
                for (int i = 0; i < 2; i++) {
                    const int row = mi * 32 + i * 16 + gid;
                    s_accum(SB, row, cpair, hh[jj][i][0]);
                    s_accum(SB, row + 8, cpair, hh[jj][i][1]);
                }
            }
        }
        // ---- u += h @ M' (slab-gated reads of HBuf) ----
        gemm_pass(d, smem, sb, buf ? OFF_H1 : OFF_H0, 1, buf, spar, mi, ni, lane, cs, cp);
    }

    BAR1();  // all warps' S contributions complete before the final GEMM reads S
    // ---- final: d = S @ (dt*W2) ----
#pragma unroll
    for (int i = 0; i < 2; i++)
#pragma unroll
        for (int j = 0; j < 8; j++)
#pragma unroll
            for (int r = 0; r < 4; r++) d[i][j][r] = 0.0f;
    gemm_pass(d, smem, sb, OFF_S, 0, 0, 0, mi, ni, lane, cs, cp);

    // ---- output: zT = z0 + d + cc ----
#pragma unroll
    for (int i = 0; i < 2; i++)
#pragma unroll
        for (int j = 0; j < 8; j++) {
            const int col = ni * 64 + j * 8 + 2 * tig;
            const int row = mi * 32 + i * 16 + gid;
            const float c0 = sT4[col].w, c1 = sT4[col + 1].w;
            float2 v0 = *(const float2*)(z0 + (size_t)(row0 + row) * 256 + col);
            float2 v1 = *(const float2*)(z0 + (size_t)(row0 + row + 8) * 256 + col);
            *(float2*)(out + (size_t)(row0 + row) * 256 + col) =
                make_float2(v0.x + d[i][j][0] + c0, v0.y + d[i][j][1] + c1);
            *(float2*)(out + (size_t)(row0 + row + 8) * 256 + col) =
                make_float2(v1.x + d[i][j][2] + c0, v1.y + d[i][j][3] + c1);
        }
}

extern "C" void kernel_launch(void* const* d_in, const int* in_sizes, int n_in,
                              void* d_out, int out_size) {
    const float* z0 = (const float*)d_in[0];
    const float* t_range = (const float*)d_in[1];
    const float* W1 = (const float*)d_in[2];
    const float* b1 = (const float*)d_in[3];
    const float* wt = (const float*)d_in[4];
    const float* W2 = (const float*)d_in[5];
    const float* b2 = (const float*)d_in[6];
    float* out = (float*)d_out;

    cudaFuncSetAttribute(ode_main, cudaFuncAttributeMaxDynamicSharedMemorySize, DYN_SMEM);
    ode_prep_mm<<<256, 256>>>(W1, W2, t_range);
    ode_prep_T<<<1, 256>>>(W1, b1, wt, b2, t_range);
    ode_prep_pack<<<24, 256>>>(W1, W2, t_range);
    ode_main<<<128, 544, DYN_SMEM>>>(z0, t_range, out);
}